// round 17
// baseline (speedup 1.0000x reference)
#include <cuda_runtime.h>
#include <cstdint>

#define NB 8
#define NN 2048
#define DF 128
#define NF 128

// ---------------- scratch (no cudaMalloc allowed) ----------------
__device__ __align__(16) float g_Y[NB * NN * DF];   // tf32(dinv[k]*X[k][f]), row-major
__device__ __align__(16) float g_D[NB * NN * DF];   // tf32(DADH), row-major
__device__ float g_dinv[NB * NN];
__device__ __align__(16) float g_part[32 * NB * NN];

// ---------------- helpers ----------------
__device__ __forceinline__ uint32_t smem_u32(const void* p) {
    uint32_t a;
    asm("{ .reg .u64 t; cvta.to.shared.u64 t, %1; cvt.u32.u64 %0, t; }" : "=r"(a) : "l"(p));
    return a;
}
__device__ __forceinline__ uint32_t f2tf(float f) {
    uint32_t u; asm("cvt.rna.tf32.f32 %0, %1;" : "=r"(u) : "f"(f)); return u;
}

#define CPA16(dst, src) \
    asm volatile("cp.async.cg.shared.global [%0], [%1], 16;" :: "r"(dst), "l"(src))
#define CPA_COMMIT() asm volatile("cp.async.commit_group;" ::: "memory")
#define CPA_WAIT(n)  asm volatile("cp.async.wait_group %0;" :: "n"(n) : "memory")

#define MMA_TF32(c, a, bq) \
    asm volatile("mma.sync.aligned.m16n8k8.row.col.f32.tf32.tf32.f32 " \
        "{%0,%1,%2,%3}, {%4,%5,%6,%7}, {%8,%9}, {%0,%1,%2,%3};" \
        : "+f"((c)[0]), "+f"((c)[1]), "+f"((c)[2]), "+f"((c)[3]) \
        : "r"((a)[0]), "r"((a)[1]), "r"((a)[2]), "r"((a)[3]), \
          "r"((bq)[0]), "r"((bq)[1]))

// ---------------- Kernel 1: column sums (read-only now) ----------------
__global__ void __launch_bounds__(256) colsum_kernel(const float* __restrict__ A)
{
    const int j4 = blockIdx.x * 256 + threadIdx.x;   // float4 col, 0..511
    const int rc = blockIdx.y;                        // 0..31
    const int b  = blockIdx.z;
    const float4* Ab = (const float4*)(A + (size_t)b * NN * NN);
    float4 s = make_float4(0.f, 0.f, 0.f, 0.f);
    const int i0 = rc * (NN / 32);
    #pragma unroll 8
    for (int i = i0; i < i0 + NN / 32; ++i) {
        float4 v = Ab[(size_t)i * (NN / 4) + j4];
        s.x += v.x; s.y += v.y; s.z += v.z; s.w += v.w;
    }
    *(float4*)(g_part + (size_t)rc * (NB * NN) + b * NN + j4 * 4) = s;
}

// ---------------- Kernel 2: dinv = rsqrt(1 + colsum) ----------------
__global__ void __launch_bounds__(256) finalize_kernel()
{
    const int idx = blockIdx.x * 256 + threadIdx.x;
    float s = 1.0f;
    #pragma unroll
    for (int rc = 0; rc < 32; ++rc) s += g_part[rc * (NB * NN) + idx];
    g_dinv[idx] = rsqrtf(s);
}

// ---------------- Kernel 3: Y = tf32(dinv[k] * X[k][f]) ----------------
__global__ void __launch_bounds__(256) scale_cvt_kernel(const float* __restrict__ X)
{
    const int idx = blockIdx.x * 256 + threadIdx.x;   // float4 index
    const int e = idx << 2;
    const int b = e >> 18;               // NN*DF = 2^18
    const int k = (e >> 7) & (NN - 1);   // DF = 2^7
    const float d = g_dinv[b * NN + k];
    float4 x = *(const float4*)(X + (size_t)e);
    uint4 y;
    y.x = f2tf(d * x.x); y.y = f2tf(d * x.y);
    y.z = f2tf(d * x.z); y.w = f2tf(d * x.w);
    *(uint4*)(g_Y + (size_t)e) = y;
}

// ---------------- Kernel 4: main tf32 GEMM: AY = A @ Y; D = d*AY + d^2*X ----------------
// block tile 64(M) x 128(N), K-step 32, 8 warps (2M x 4N), warp tile 32x32.
// smem = 53KB -> 3 CTAs/SM. Also streams A tiles to outA (copy fused here).
#define LDA 36
#define LDB 136
#define SA_FLOATS (2 * 64 * LDA)      // 4608
#define SB_FLOATS (2 * 32 * LDB)      // 8704
#define SMEM_MAIN ((SA_FLOATS + SB_FLOATS) * 4)    // 53248 B

__global__ void __launch_bounds__(256, 3) gcn_mma_kernel(
    const float* __restrict__ A, const float* __restrict__ X,
    float* __restrict__ outA)
{
    extern __shared__ float sm[];
    float* sA = sm;                          // [2][64][LDA]
    float* sB = sm + SA_FLOATS;              // [2][32][LDB]

    const uint32_t smbA = smem_u32(sA);
    const uint32_t smbB = smem_u32(sB);

    const int tid  = threadIdx.x;
    const int wid  = tid >> 5;
    const int lane = tid & 31;
    const int b     = blockIdx.y;
    const int mBase = blockIdx.x * 64;
    const int warpM = (wid >> 2) * 32;     // 0 or 32
    const int warpN = (wid & 3) * 32;      // 0,32,64,96
    const int gr = lane >> 2;              // 0..7
    const int gc = lane & 3;               // 0..3

    const float* Ab = A + (size_t)b * NN * NN + (size_t)mBase * NN;
    const float* Yb = g_Y + (size_t)b * NN * DF;
    float* OAb = outA ? outA + (size_t)b * NN * NN + (size_t)mBase * NN : nullptr;

    float acc[2][4][4];
    #pragma unroll
    for (int mf = 0; mf < 2; ++mf)
        #pragma unroll
        for (int nf = 0; nf < 4; ++nf)
            #pragma unroll
            for (int q = 0; q < 4; ++q) acc[mf][nf][q] = 0.f;

    // per-thread A-tile slice (also used for the outA passthrough)
    const int arow0 = tid >> 3;            // c = tid
    const int acol0 = (tid & 7) << 2;
    const int arow1 = (tid + 256) >> 3;    // c = tid + 256
    const int acol1 = ((tid + 256) & 7) << 2;   // == acol0

    auto load_stage = [&](int st, int k0) {
        CPA16(smbA + ((st * 64 * LDA + arow0 * LDA + acol0) << 2),
              Ab + (size_t)arow0 * NN + k0 + acol0);
        CPA16(smbA + ((st * 64 * LDA + arow1 * LDA + acol1) << 2),
              Ab + (size_t)arow1 * NN + k0 + acol1);
        #pragma unroll
        for (int t = 0; t < 4; ++t) {
            int c = t * 256 + tid;
            int row = c >> 5, col4 = (c & 31) << 2;
            CPA16(smbB + ((st * 32 * LDB + row * LDB + col4) << 2),
                  Yb + (size_t)(k0 + row) * DF + col4);
        }
    };

    load_stage(0, 0);
    CPA_COMMIT();

    for (int c = 0; c < NN / 32; ++c) {
        const int st = c & 1;
        const int k0 = c * 32;
        if (c + 1 < NN / 32) {
            load_stage((c + 1) & 1, k0 + 32);
            CPA_COMMIT();
            CPA_WAIT(1);
        } else {
            CPA_WAIT(0);
        }
        __syncthreads();

        const float* pA = sA + st * 64 * LDA;
        const float* pB = sB + st * 32 * LDB;

        // fused A copy: smem -> outA (same slice this thread cp.async'd)
        if (OAb) {
            float4 v0 = *(const float4*)(pA + arow0 * LDA + acol0);
            float4 v1 = *(const float4*)(pA + arow1 * LDA + acol1);
            *(float4*)(OAb + (size_t)arow0 * NN + k0 + acol0) = v0;
            *(float4*)(OAb + (size_t)arow1 * NN + k0 + acol1) = v1;
        }

        #pragma unroll
        for (int ks = 0; ks < 4; ++ks) {
            const int kc = ks * 8 + gc;
            uint32_t aF[2][4], bF[4][2];
            #pragma unroll
            for (int mf = 0; mf < 2; ++mf) {
                int r = warpM + mf * 16 + gr;
                aF[mf][0] = f2tf(pA[r * LDA + kc]);
                aF[mf][1] = f2tf(pA[(r + 8) * LDA + kc]);
                aF[mf][2] = f2tf(pA[r * LDA + kc + 4]);
                aF[mf][3] = f2tf(pA[(r + 8) * LDA + kc + 4]);
            }
            #pragma unroll
            for (int nf = 0; nf < 4; ++nf) {
                int n = warpN + nf * 8 + gr;
                bF[nf][0] = __float_as_uint(pB[kc * LDB + n]);
                bF[nf][1] = __float_as_uint(pB[(kc + 4) * LDB + n]);
            }
            #pragma unroll
            for (int mf = 0; mf < 2; ++mf)
                #pragma unroll
                for (int nf = 0; nf < 4; ++nf)
                    MMA_TF32(acc[mf][nf], aF[mf], bF[nf]);
        }
        __syncthreads();
    }

    // ---- epilogue: D = tf32(d_i*acc + d_i^2*X) -> g_D ----
    const float* Xb = X + (size_t)b * NN * DF;
    float* Db = g_D + (size_t)b * NN * DF;
    #pragma unroll
    for (int mf = 0; mf < 2; ++mf) {
        const int g0 = mBase + warpM + mf * 16 + gr;
        const float d0 = g_dinv[b * NN + g0];
        const float d1 = g_dinv[b * NN + g0 + 8];
        #pragma unroll
        for (int nf = 0; nf < 4; ++nf) {
            const int col = warpN + nf * 8 + 2 * gc;
            float2 x0 = *(const float2*)(Xb + (size_t)g0 * DF + col);
            float2 x1 = *(const float2*)(Xb + (size_t)(g0 + 8) * DF + col);
            uint32_t v00 = f2tf(d0 * acc[mf][nf][0] + d0 * d0 * x0.x);
            uint32_t v01 = f2tf(d0 * acc[mf][nf][1] + d0 * d0 * x0.y);
            uint32_t v10 = f2tf(d1 * acc[mf][nf][2] + d1 * d1 * x1.x);
            uint32_t v11 = f2tf(d1 * acc[mf][nf][3] + d1 * d1 * x1.y);
            *(uint2*)(Db + (size_t)g0 * DF + col)       = make_uint2(v00, v01);
            *(uint2*)(Db + (size_t)(g0 + 8) * DF + col) = make_uint2(v10, v11);
        }
    }
}

// ---------------- Kernel 5: H = relu(D @ W) ----------------
// grid (NN/128, NB), block 256, 8 warps (2M x 4N), warp tile 64x32. K=128.
#define LDD2 132
#define LDW2 136
#define SMEM_WG ((128 * LDD2 + 128 * LDW2) * 4)   // 137216 B

__global__ void __launch_bounds__(256, 1) wgemm_kernel(
    const float* __restrict__ W, float* __restrict__ outH)
{
    extern __shared__ float sm[];
    float* sD = sm;                 // [128][LDD2] (tf32 bits)
    float* sW = sm + 128 * LDD2;    // [128][LDW2] (tf32 bits)

    const int tid  = threadIdx.x;
    const int wid  = tid >> 5;
    const int lane = tid & 31;
    const int b     = blockIdx.y;
    const int mBase = blockIdx.x * 128;
    const int warpM = (wid >> 2) * 64;     // 0 or 64
    const int warpN = (wid & 3) * 32;      // 0,32,64,96
    const int gr = lane >> 2;
    const int gc = lane & 3;

    const float* Db = g_D + (size_t)b * NN * DF + (size_t)mBase * DF;

    // load D tile (already tf32) and W (convert) into smem
    for (int i = tid * 4; i < 128 * DF; i += 1024) {
        int row = i >> 7, col = i & 127;
        float4 v = *(const float4*)(Db + (size_t)row * DF + col);
        *(float4*)(sD + row * LDD2 + col) = v;
    }
    for (int i = tid * 4; i < 128 * NF; i += 1024) {
        int d = i >> 7, f = i & 127;
        float4 w = *(const float4*)(W + d * NF + f);
        uint4 u;
        u.x = f2tf(w.x); u.y = f2tf(w.y); u.z = f2tf(w.z); u.w = f2tf(w.w);
        *(uint4*)(sW + d * LDW2 + f) = u;
    }
    __syncthreads();

    float h[4][4][4];
    #pragma unroll
    for (int mf = 0; mf < 4; ++mf)
        #pragma unroll
        for (int nf = 0; nf < 4; ++nf)
            #pragma unroll
            for (int q = 0; q < 4; ++q) h[mf][nf][q] = 0.f;

    #pragma unroll
    for (int ks = 0; ks < 16; ++ks) {
        const int kc = ks * 8 + gc;
        uint32_t aF[4][4], bF[4][2];
        #pragma unroll
        for (int mf = 0; mf < 4; ++mf) {
            int r = warpM + mf * 16 + gr;
            aF[mf][0] = __float_as_uint(sD[r * LDD2 + kc]);
            aF[mf][1] = __float_as_uint(sD[(r + 8) * LDD2 + kc]);
            aF[mf][2] = __float_as_uint(sD[r * LDD2 + kc + 4]);
            aF[mf][3] = __float_as_uint(sD[(r + 8) * LDD2 + kc + 4]);
        }
        #pragma unroll
        for (int nf = 0; nf < 4; ++nf) {
            int n = warpN + nf * 8 + gr;
            bF[nf][0] = __float_as_uint(sW[kc * LDW2 + n]);
            bF[nf][1] = __float_as_uint(sW[(kc + 4) * LDW2 + n]);
        }
        #pragma unroll
        for (int mf = 0; mf < 4; ++mf)
            #pragma unroll
            for (int nf = 0; nf < 4; ++nf)
                MMA_TF32(h[mf][nf], aF[mf], bF[nf]);
    }

    float* Hb = outH + (size_t)b * NN * NF + (size_t)mBase * NF;
    #pragma unroll
    for (int mf = 0; mf < 4; ++mf) {
        const int r = warpM + mf * 16 + gr;
        #pragma unroll
        for (int nf = 0; nf < 4; ++nf) {
            const int col = warpN + nf * 8 + 2 * gc;
            float2 o0 = make_float2(fmaxf(h[mf][nf][0], 0.f), fmaxf(h[mf][nf][1], 0.f));
            float2 o1 = make_float2(fmaxf(h[mf][nf][2], 0.f), fmaxf(h[mf][nf][3], 0.f));
            *(float2*)(Hb + (size_t)r * NF + col)       = o0;
            *(float2*)(Hb + (size_t)(r + 8) * NF + col) = o1;
        }
    }
}

// ---------------- host ----------------
extern "C" void kernel_launch(void* const* d_in, const int* in_sizes, int n_in,
                              void* d_out, int out_size)
{
    const float* A = (const float*)d_in[0];
    const float* X = (const float*)d_in[1];
    const float* W = (const float*)d_in[2];
    float* out = (float*)d_out;

    const long long A_ELEMS = (long long)NB * NN * NN;
    const long long H_ELEMS = (long long)NB * NN * NF;
    float* outA = nullptr;
    float* outH = out;
    if ((long long)out_size >= A_ELEMS + H_ELEMS) {
        outA = out;
        outH = out + ((long long)out_size - H_ELEMS);
    }

    cudaFuncSetAttribute(gcn_mma_kernel,
                         cudaFuncAttributeMaxDynamicSharedMemorySize, SMEM_MAIN);
    cudaFuncSetAttribute(wgemm_kernel,
                         cudaFuncAttributeMaxDynamicSharedMemorySize, SMEM_WG);

    dim3 g1(2, 32, NB);
    colsum_kernel<<<g1, 256>>>(A);

    finalize_kernel<<<(NB * NN) / 256, 256>>>();

    scale_cvt_kernel<<<(NB * NN * DF / 4) / 256, 256>>>(X);

    dim3 g4(NN / 64, NB);
    gcn_mma_kernel<<<g4, 256, SMEM_MAIN>>>(A, X, outA);

    dim3 g5(NN / 128, NB);
    wgemm_kernel<<<g5, 256, SMEM_WG>>>(W, outH);
}